// round 1
// baseline (speedup 1.0000x reference)
#include <cuda_runtime.h>
#include <cstdint>

#define BN      65536       // B*N total points
#define NPTS    512         // points per batch
#define NBATCH  128
#define KNN     16
#define HID     128         // H
#define DOUT    64          // D
#define FEAT    32          // F
#define H1STR   129         // padded h1 row stride (odd -> conflict-free phase B)
#define PTS     8           // points per block in edge kernel
#define NGROUPS (BN / PTS)  // 8192

// Scratch (allocation-free rule: __device__ globals)
__device__ float g_P[BN * HID];       // 33.5 MB
__device__ float g_Q[BN * HID];       // 33.5 MB
__device__ int   g_nbr[BN * KNN];     // 4 MB

// ---------------------------------------------------------------------------
// Kernel 1: KNN. One block per batch. Select 17 smallest (d^2, j) lexicographic
// (matches stable argsort incl. ties), drop rank 0 (self, d=0).
// Top-17 list lives in registers via fully-unrolled compare-swap insertion.
// ---------------------------------------------------------------------------
__global__ void __launch_bounds__(NPTS) knn_kernel(const float* __restrict__ events) {
    __shared__ float xs[NPTS], ys[NPTS];
    int b = blockIdx.x;
    int i = threadIdx.x;
    const float* ev = events + (size_t)b * NPTS * FEAT;
    xs[i] = ev[i * FEAT + 0];
    ys[i] = ev[i * FEAT + 1];
    __syncthreads();

    float xi = xs[i], yi = ys[i];
    float bd[17]; int bi[17];
#pragma unroll
    for (int s = 0; s < 17; s++) { bd[s] = 3.4e38f; bi[s] = 0x7fffffff; }

    for (int j = 0; j < NPTS; j++) {
        float dx = xi - xs[j];
        float dy = yi - ys[j];
        float d2 = dx * dx + dy * dy;
        // only enter (rare) insertion path if strictly better than worst slot
        if (d2 < bd[16] || (d2 == bd[16] && j < bi[16])) {
            float cd = d2; int cj = j;
#pragma unroll
            for (int s = 0; s < 17; s++) {
                bool lt = (cd < bd[s]) || (cd == bd[s] && cj < bi[s]);
                float od = bd[s]; int oj = bi[s];
                bd[s] = lt ? cd : od;
                bi[s] = lt ? cj : oj;
                cd    = lt ? od : cd;
                cj    = lt ? oj : cj;
            }
        }
    }
    int* o = g_nbr + ((size_t)b * NPTS + i) * KNN;
#pragma unroll
    for (int s = 0; s < KNN; s++) o[s] = bi[s + 1];   // skip self (rank 0)
}

// ---------------------------------------------------------------------------
// Kernel 2: P = x @ (W1a - W1b) + b1 ; Q = x @ W1b.  Warp per point.
// ---------------------------------------------------------------------------
__global__ void __launch_bounds__(256) pq_kernel(const float* __restrict__ events,
                                                 const float* __restrict__ W1,
                                                 const float* __restrict__ b1) {
    __shared__ float4 wa[FEAT][32];   // W1 rows 0..31  (x part)
    __shared__ float4 wb[FEAT][32];   // W1 rows 32..63 (nbr-x part)
    int t = threadIdx.x;
    const float4* w4 = (const float4*)W1;   // 64 rows x 32 float4
    for (int u = t; u < 2048; u += 256) {
        int f = u >> 5, c = u & 31;
        float4 v = w4[u];
        if (f < FEAT) wa[f][c] = v; else wb[f - FEAT][c] = v;
    }
    __syncthreads();

    int w = t >> 5, lane = t & 31;
    size_t pt = (size_t)blockIdx.x * 8 + w;
    float ev = events[pt * FEAT + lane];

    float4 aA = {0.f, 0.f, 0.f, 0.f};
    float4 aB = {0.f, 0.f, 0.f, 0.f};
#pragma unroll
    for (int f = 0; f < FEAT; f++) {
        float ef = __shfl_sync(0xffffffffu, ev, f);
        float4 a = wa[f][lane];
        float4 b = wb[f][lane];
        aA.x = fmaf(ef, a.x, aA.x); aA.y = fmaf(ef, a.y, aA.y);
        aA.z = fmaf(ef, a.z, aA.z); aA.w = fmaf(ef, a.w, aA.w);
        aB.x = fmaf(ef, b.x, aB.x); aB.y = fmaf(ef, b.y, aB.y);
        aB.z = fmaf(ef, b.z, aB.z); aB.w = fmaf(ef, b.w, aB.w);
    }
    float4 bv = ((const float4*)b1)[lane];
    float4 p;
    p.x = aA.x - aB.x + bv.x; p.y = aA.y - aB.y + bv.y;
    p.z = aA.z - aB.z + bv.z; p.w = aA.w - aB.w + bv.w;
    ((float4*)g_P)[pt * 32 + lane] = p;
    ((float4*)g_Q)[pt * 32 + lane] = aB;
}

// ---------------------------------------------------------------------------
// Kernel 3: fused gather + relu + (16x128)@(128x64) + relu + mean over k.
// Warp per point, 8 points per block. Register blocking: 4 k x 8 d per thread.
// ---------------------------------------------------------------------------
__global__ void __launch_bounds__(256, 2) edge_kernel(const float* __restrict__ W2,
                                                      const float* __restrict__ b2,
                                                      float* __restrict__ out) {
    extern __shared__ float smem[];
    float* w2s  = smem;                               // 8192 floats (32 KB)
    float* p_sm = w2s + HID * DOUT;                   // PTS*128
    float* h1   = p_sm + PTS * HID;                   // PTS*16*129
    int*   nbr_sm = (int*)(h1 + PTS * KNN * H1STR);   // PTS*16

    int t = threadIdx.x;
    int w = t >> 5, lane = t & 31;
    int kg = lane >> 3, dg = lane & 7;

    // W2 into smem once per block (viewed as [128][16] float4)
    for (int u = t; u < HID * DOUT / 4; u += 256)
        ((float4*)w2s)[u] = ((const float4*)W2)[u];

    float b2v[8];
#pragma unroll
    for (int dd = 0; dd < 8; dd++) b2v[dd] = b2[dg * 8 + dd];

    for (int g = blockIdx.x; g < NGROUPS; g += gridDim.x) {
        int g8 = g * PTS;
        __syncthreads();   // also covers W2 load on first iteration
        // stage P rows + neighbor lists
        for (int u = t; u < PTS * HID; u += 256)
            p_sm[u] = g_P[(size_t)g8 * HID + u];
        if (t < PTS * KNN)
            nbr_sm[t] = g_nbr[(size_t)g8 * KNN + t];
        __syncthreads();

        // ---- phase A: h1[k][h] = relu(P_i[h] + Q_nbr[h]) (warp w = point w)
        {
            int qbase = g8 & ~(NPTS - 1);             // batch base (PTS | NPTS)
            const float* pp  = p_sm + w * HID;
            float*       h1p = h1 + w * (KNN * H1STR);
            for (int k = 0; k < KNN; k++) {
                int j = nbr_sm[w * KNN + k];
                const float* qr = g_Q + ((size_t)qbase + j) * HID;
#pragma unroll
                for (int c = 0; c < 4; c++) {
                    int hh = lane + 32 * c;
                    float v = pp[hh] + qr[hh];
                    h1p[k * H1STR + hh] = fmaxf(v, 0.0f);
                }
            }
        }
        __syncthreads();

        // ---- phase B: acc[kk][dd] over h; k = kg + 4*kk, d = dg*8 + dd
        float acc[4][8];
#pragma unroll
        for (int a = 0; a < 4; a++)
#pragma unroll
            for (int dd = 0; dd < 8; dd++) acc[a][dd] = 0.0f;

        const float*  h1w = h1 + w * (KNN * H1STR);
        const float4* w2f = (const float4*)w2s;
#pragma unroll 2
        for (int h = 0; h < HID; h++) {
            float a0 = h1w[(kg     ) * H1STR + h];
            float a1 = h1w[(kg +  4) * H1STR + h];
            float a2 = h1w[(kg +  8) * H1STR + h];
            float a3 = h1w[(kg + 12) * H1STR + h];
            float4 w0 = w2f[h * 16 + dg * 2];
            float4 w1 = w2f[h * 16 + dg * 2 + 1];
            float wv[8] = {w0.x, w0.y, w0.z, w0.w, w1.x, w1.y, w1.z, w1.w};
#pragma unroll
            for (int dd = 0; dd < 8; dd++) {
                acc[0][dd] = fmaf(a0, wv[dd], acc[0][dd]);
                acc[1][dd] = fmaf(a1, wv[dd], acc[1][dd]);
                acc[2][dd] = fmaf(a2, wv[dd], acc[2][dd]);
                acc[3][dd] = fmaf(a3, wv[dd], acc[3][dd]);
            }
        }

        // relu(+b2) per k, sum local 4 k, shuffle-reduce across 4 k-groups
        float s[8];
#pragma unroll
        for (int dd = 0; dd < 8; dd++) {
            s[dd] = fmaxf(acc[0][dd] + b2v[dd], 0.0f)
                  + fmaxf(acc[1][dd] + b2v[dd], 0.0f)
                  + fmaxf(acc[2][dd] + b2v[dd], 0.0f)
                  + fmaxf(acc[3][dd] + b2v[dd], 0.0f);
        }
#pragma unroll
        for (int dd = 0; dd < 8; dd++) {
            s[dd] += __shfl_xor_sync(0xffffffffu, s[dd], 8);
            s[dd] += __shfl_xor_sync(0xffffffffu, s[dd], 16);
        }
        if (kg == 0) {
            float* op = out + ((size_t)(g8 + w)) * DOUT + dg * 8;
            float4 v0 = {s[0] * 0.0625f, s[1] * 0.0625f, s[2] * 0.0625f, s[3] * 0.0625f};
            float4 v1 = {s[4] * 0.0625f, s[5] * 0.0625f, s[6] * 0.0625f, s[7] * 0.0625f};
            ((float4*)op)[0] = v0;
            ((float4*)op)[1] = v1;
        }
    }
}

// ---------------------------------------------------------------------------
extern "C" void kernel_launch(void* const* d_in, const int* in_sizes, int n_in,
                              void* d_out, int out_size) {
    const float* events = (const float*)d_in[0];   // (128,512,32)
    const float* W1     = (const float*)d_in[1];   // (64,128)
    const float* b1     = (const float*)d_in[2];   // (128)
    const float* W2     = (const float*)d_in[3];   // (128,64)
    const float* b2     = (const float*)d_in[4];   // (64)
    float* out = (float*)d_out;                    // (128,512,64)

    const int smem3 = (HID * DOUT + PTS * HID + PTS * KNN * H1STR) * 4 + PTS * KNN * 4;
    cudaFuncSetAttribute(edge_kernel, cudaFuncAttributeMaxDynamicSharedMemorySize, smem3);

    knn_kernel<<<NBATCH, NPTS>>>(events);
    pq_kernel<<<BN / 8, 256>>>(events, W1, b1);
    edge_kernel<<<2048, 256, smem3>>>(W2, b2, out);
}

// round 4
// speedup vs baseline: 1.2053x; 1.2053x over previous
#include <cuda_runtime.h>
#include <cstdint>

#define BN      65536       // B*N total points
#define NPTS    512         // points per batch
#define NBATCH  128
#define KNN     16
#define HID     128         // H
#define DOUT    64          // D
#define FEAT    32          // F
#define H1STR   132         // padded h1 row stride (16B-aligned rows, conflict-free)
#define PTS     8           // points per block in edge kernel
#define NGROUPS (BN / PTS)  // 8192
#define KBLK    128         // threads per knn block

// Scratch (allocation-free rule: __device__ globals)
__device__ float g_P[BN * HID];       // 33.5 MB
__device__ float g_Q[BN * HID];       // 33.5 MB
__device__ int   g_nbr[BN * KNN];     // 4 MB

// ---------------------------------------------------------------------------
// Kernel 1: KNN. 4 blocks per batch (128 points each), coords in smem.
// Top-17 by d^2 with STRICT < insertion while scanning j ascending ==
// stable argsort order (ties keep smaller j first). Drop rank 0 (self).
// ---------------------------------------------------------------------------
__global__ void __launch_bounds__(KBLK) knn_kernel(const float* __restrict__ events) {
    __shared__ float xs[NPTS], ys[NPTS];
    int b   = blockIdx.x >> 2;
    int seg = (blockIdx.x & 3) * KBLK;
    const float* ev = events + (size_t)b * NPTS * FEAT;
    for (int u = threadIdx.x; u < NPTS; u += KBLK) {
        xs[u] = ev[u * FEAT + 0];
        ys[u] = ev[u * FEAT + 1];
    }
    __syncthreads();

    int i = seg + threadIdx.x;
    float xi = xs[i], yi = ys[i];
    float bd[17]; int bi[17];
#pragma unroll
    for (int s = 0; s < 17; s++) { bd[s] = 3.4e38f; bi[s] = 0; }

    for (int j = 0; j < NPTS; j++) {
        float dx = xi - xs[j];
        float dy = yi - ys[j];
        float d2 = fmaf(dx, dx, dy * dy);
        if (d2 < bd[16]) {
            float cd = d2; int cj = j;
#pragma unroll
            for (int s = 0; s < 17; s++) {
                bool lt = cd < bd[s];          // strict: ties keep earlier j
                float od = bd[s]; int oj = bi[s];
                bd[s] = lt ? cd : od;
                bi[s] = lt ? cj : oj;
                cd    = lt ? od : cd;
                cj    = lt ? oj : cj;
            }
        }
    }
    int* o = g_nbr + ((size_t)b * NPTS + i) * KNN;
#pragma unroll
    for (int s = 0; s < KNN; s++) o[s] = bi[s + 1];   // skip self (rank 0)
}

// ---------------------------------------------------------------------------
// Kernel 2: P = x @ (W1a - W1b) + b1 ; Q = x @ W1b.  Warp per point.
// ---------------------------------------------------------------------------
__global__ void __launch_bounds__(256) pq_kernel(const float* __restrict__ events,
                                                 const float* __restrict__ W1,
                                                 const float* __restrict__ b1) {
    __shared__ float4 wa[FEAT][32];   // W1 rows 0..31  (x part)
    __shared__ float4 wb[FEAT][32];   // W1 rows 32..63 (nbr-x part)
    int t = threadIdx.x;
    const float4* w4 = (const float4*)W1;   // 64 rows x 32 float4
    for (int u = t; u < 2048; u += 256) {
        int f = u >> 5, c = u & 31;
        float4 v = w4[u];
        if (f < FEAT) wa[f][c] = v; else wb[f - FEAT][c] = v;
    }
    __syncthreads();

    int w = t >> 5, lane = t & 31;
    size_t pt = (size_t)blockIdx.x * 8 + w;
    float ev = events[pt * FEAT + lane];

    float4 aA = {0.f, 0.f, 0.f, 0.f};
    float4 aB = {0.f, 0.f, 0.f, 0.f};
#pragma unroll
    for (int f = 0; f < FEAT; f++) {
        float ef = __shfl_sync(0xffffffffu, ev, f);
        float4 a = wa[f][lane];
        float4 b = wb[f][lane];
        aA.x = fmaf(ef, a.x, aA.x); aA.y = fmaf(ef, a.y, aA.y);
        aA.z = fmaf(ef, a.z, aA.z); aA.w = fmaf(ef, a.w, aA.w);
        aB.x = fmaf(ef, b.x, aB.x); aB.y = fmaf(ef, b.y, aB.y);
        aB.z = fmaf(ef, b.z, aB.z); aB.w = fmaf(ef, b.w, aB.w);
    }
    float4 bv = ((const float4*)b1)[lane];
    float4 p;
    p.x = aA.x - aB.x + bv.x; p.y = aA.y - aB.y + bv.y;
    p.z = aA.z - aB.z + bv.z; p.w = aA.w - aB.w + bv.w;
    ((float4*)g_P)[pt * 32 + lane] = p;
    ((float4*)g_Q)[pt * 32 + lane] = aB;
}

// ---------------------------------------------------------------------------
// Kernel 3: fused gather + relu + (16x128)@(128x64) + relu + mean over k.
// Warp per point, 8 points per block. Phase B uses packed fp32x2 FMA (FFMA2).
// W2 row = 64 floats = 256 B = 16 ulonglong2 (stride 16, NOT 8 — R2 bug).
// ---------------------------------------------------------------------------
__device__ __forceinline__ unsigned long long dup_f32(float s) {
    unsigned long long r;
    asm("mov.b64 %0, {%1, %1};" : "=l"(r) : "r"(__float_as_uint(s)));
    return r;
}
__device__ __forceinline__ void fma2(unsigned long long& acc,
                                     unsigned long long a, unsigned long long b) {
    asm("fma.rn.f32x2 %0, %1, %2, %0;" : "+l"(acc) : "l"(a), "l"(b));
}
__device__ __forceinline__ void unpack2(unsigned long long v, float& lo, float& hi) {
    unsigned l, h;
    asm("mov.b64 {%0, %1}, %2;" : "=r"(l), "=r"(h) : "l"(v));
    lo = __uint_as_float(l); hi = __uint_as_float(h);
}

__global__ void __launch_bounds__(256, 2) edge_kernel(const float* __restrict__ W2,
                                                      const float* __restrict__ b2,
                                                      float* __restrict__ out) {
    extern __shared__ float smem[];
    float* w2s  = smem;                               // 8192 floats (32 KB)
    float* p_sm = w2s + HID * DOUT;                   // PTS*128
    float* h1   = p_sm + PTS * HID;                   // PTS*16*132
    int*   nbr_sm = (int*)(h1 + PTS * KNN * H1STR);   // PTS*16

    int t = threadIdx.x;
    int w = t >> 5, lane = t & 31;
    int kg = lane >> 3, dg = lane & 7;

    // W2 into smem once per block
    for (int u = t; u < HID * DOUT / 4; u += 256)
        ((float4*)w2s)[u] = ((const float4*)W2)[u];

    float b2v[8];
#pragma unroll
    for (int dd = 0; dd < 8; dd++) b2v[dd] = b2[dg * 8 + dd];

    for (int g = blockIdx.x; g < NGROUPS; g += gridDim.x) {
        int g8 = g * PTS;
        __syncthreads();   // also covers W2 load on first iteration
        for (int u = t; u < PTS * HID; u += 256)
            p_sm[u] = g_P[(size_t)g8 * HID + u];
        if (t < PTS * KNN)
            nbr_sm[t] = g_nbr[(size_t)g8 * KNN + t];
        __syncthreads();

        // ---- phase A: h1[k][h] = relu(P_i[h] + Q_nbr[h]) (warp w = point w)
        {
            int qbase = g8 & ~(NPTS - 1);             // batch base
            const float* pp  = p_sm + w * HID;
            float*       h1p = h1 + w * (KNN * H1STR);
            for (int k = 0; k < KNN; k++) {
                int j = nbr_sm[w * KNN + k];
                const float* qr = g_Q + ((size_t)qbase + j) * HID;
#pragma unroll
                for (int c = 0; c < 4; c++) {
                    int hh = lane + 32 * c;
                    float v = pp[hh] + __ldg(qr + hh);
                    h1p[k * H1STR + hh] = fmaxf(v, 0.0f);
                }
            }
        }
        __syncthreads();

        // ---- phase B: packed-pair accumulate. acc2[kk][p] = (d=2p, d=2p+1)
        unsigned long long acc2[4][4];
#pragma unroll
        for (int a = 0; a < 4; a++)
#pragma unroll
            for (int p = 0; p < 4; p++) acc2[a][p] = 0ull;

        const float* h1w = h1 + w * (KNN * H1STR);
        const float4* a0p = (const float4*)(h1w + (kg     ) * H1STR);
        const float4* a1p = (const float4*)(h1w + (kg +  4) * H1STR);
        const float4* a2p = (const float4*)(h1w + (kg +  8) * H1STR);
        const float4* a3p = (const float4*)(h1w + (kg + 12) * H1STR);
        const ulonglong2* w2u = (const ulonglong2*)w2s;   // row = 16 ull2

#define EK_STEP(COMP, HH)                                                     \
        {                                                                     \
            ulonglong2 wA = w2u[(HH) * 16 + dg * 2];                          \
            ulonglong2 wB = w2u[(HH) * 16 + dg * 2 + 1];                      \
            unsigned long long s0 = dup_f32(a0.COMP);                         \
            unsigned long long s1 = dup_f32(a1.COMP);                         \
            unsigned long long s2 = dup_f32(a2.COMP);                         \
            unsigned long long s3 = dup_f32(a3.COMP);                         \
            fma2(acc2[0][0], s0, wA.x); fma2(acc2[0][1], s0, wA.y);           \
            fma2(acc2[0][2], s0, wB.x); fma2(acc2[0][3], s0, wB.y);           \
            fma2(acc2[1][0], s1, wA.x); fma2(acc2[1][1], s1, wA.y);           \
            fma2(acc2[1][2], s1, wB.x); fma2(acc2[1][3], s1, wB.y);           \
            fma2(acc2[2][0], s2, wA.x); fma2(acc2[2][1], s2, wA.y);           \
            fma2(acc2[2][2], s2, wB.x); fma2(acc2[2][3], s2, wB.y);           \
            fma2(acc2[3][0], s3, wA.x); fma2(acc2[3][1], s3, wA.y);           \
            fma2(acc2[3][2], s3, wB.x); fma2(acc2[3][3], s3, wB.y);           \
        }

#pragma unroll 4
        for (int hq = 0; hq < HID / 4; hq++) {
            float4 a0 = a0p[hq], a1 = a1p[hq], a2 = a2p[hq], a3 = a3p[hq];
            EK_STEP(x, hq * 4 + 0)
            EK_STEP(y, hq * 4 + 1)
            EK_STEP(z, hq * 4 + 2)
            EK_STEP(w, hq * 4 + 3)
        }
#undef EK_STEP

        // relu(+b2) per k, sum 4 local k, shuffle-reduce across 4 k-groups
        float s[8];
#pragma unroll
        for (int p = 0; p < 4; p++) {
            float v0l, v0h, v1l, v1h, v2l, v2h, v3l, v3h;
            unpack2(acc2[0][p], v0l, v0h);
            unpack2(acc2[1][p], v1l, v1h);
            unpack2(acc2[2][p], v2l, v2h);
            unpack2(acc2[3][p], v3l, v3h);
            float bl = b2v[2 * p], bh = b2v[2 * p + 1];
            s[2 * p] = fmaxf(v0l + bl, 0.0f) + fmaxf(v1l + bl, 0.0f)
                     + fmaxf(v2l + bl, 0.0f) + fmaxf(v3l + bl, 0.0f);
            s[2 * p + 1] = fmaxf(v0h + bh, 0.0f) + fmaxf(v1h + bh, 0.0f)
                         + fmaxf(v2h + bh, 0.0f) + fmaxf(v3h + bh, 0.0f);
        }
#pragma unroll
        for (int dd = 0; dd < 8; dd++) {
            s[dd] += __shfl_xor_sync(0xffffffffu, s[dd], 8);
            s[dd] += __shfl_xor_sync(0xffffffffu, s[dd], 16);
        }
        if (kg == 0) {
            float* op = out + ((size_t)(g8 + w)) * DOUT + dg * 8;
            float4 v0 = {s[0] * 0.0625f, s[1] * 0.0625f, s[2] * 0.0625f, s[3] * 0.0625f};
            float4 v1 = {s[4] * 0.0625f, s[5] * 0.0625f, s[6] * 0.0625f, s[7] * 0.0625f};
            ((float4*)op)[0] = v0;
            ((float4*)op)[1] = v1;
        }
    }
}

// ---------------------------------------------------------------------------
extern "C" void kernel_launch(void* const* d_in, const int* in_sizes, int n_in,
                              void* d_out, int out_size) {
    const float* events = (const float*)d_in[0];   // (128,512,32)
    const float* W1     = (const float*)d_in[1];   // (64,128)
    const float* b1     = (const float*)d_in[2];   // (128)
    const float* W2     = (const float*)d_in[3];   // (128,64)
    const float* b2     = (const float*)d_in[4];   // (64)
    float* out = (float*)d_out;                    // (128,512,64)

    const int smem3 = (HID * DOUT + PTS * HID + PTS * KNN * H1STR) * 4 + PTS * KNN * 4;
    cudaFuncSetAttribute(edge_kernel, cudaFuncAttributeMaxDynamicSharedMemorySize, smem3);

    knn_kernel<<<NBATCH * 4, KBLK>>>(events);
    pq_kernel<<<BN / 8, 256>>>(events, W1, b1);
    edge_kernel<<<296, 256, smem3>>>(W2, b2, out);
}

// round 6
// speedup vs baseline: 1.4087x; 1.1688x over previous
#include <cuda_runtime.h>
#include <cstdint>

#define BN      65536       // B*N total points
#define NPTS    512         // points per batch
#define NBATCH  128
#define KNN     16
#define HID     128         // H
#define DOUT    64          // D
#define FEAT    32          // F
#define H1STR   132         // padded h1 row stride (16B-aligned rows)
#define EGRID   296         // edge blocks (2/SM)
#define EWARPS  (EGRID * 8) // 2368 streaming warps
#define KNNBLK  512         // knn blocks in fused kernel
#define PQBLK   8192        // pq blocks in fused kernel

// Scratch (allocation-free rule: __device__ globals)
__device__ float g_P[BN * HID];       // 33.5 MB
__device__ float g_Q[BN * HID];       // 33.5 MB
__device__ int   g_nbr[BN * KNN];     // 4 MB

// ---------------------------------------------------------------------------
// Fused kernel 1: blocks [0,512) do KNN (2 threads/point, 128 points/block);
// blocks [512, 512+8192) do the P/Q GEMM (warp per point).
//
// KNN: each thread scans 256 candidates keeping sorted top-17 by (d2, j)
// (strict-< insert on ascending j == stable argsort order). Chain uses
// FMNMX (fma pipe) + SEL (alu pipe) to split pipe pressure. The two
// half-lists merge via the bitonic top-K identity C[s]=min(A[s],B[16-s])
// (A = low-j half wins value ties -> exact lexicographic set). The
// lexicographic-min of C (self or d=0 duplicate) is dropped; remaining 16
// are the neighbor SET (order irrelevant: output is a mean over k).
// ---------------------------------------------------------------------------
__global__ void __launch_bounds__(256) knn_pq_kernel(const float* __restrict__ events,
                                                     const float* __restrict__ W1,
                                                     const float* __restrict__ b1) {
    __shared__ float sbuf[8192];   // 32 KB: knn -> float2[512]; pq -> float4[2048]
    int t = threadIdx.x;

    if (blockIdx.x < KNNBLK) {
        // ================= KNN =================
        float2* s_xy = (float2*)sbuf;
        int b   = blockIdx.x >> 2;
        int seg = (blockIdx.x & 3) * 128;
        const float* ev = events + (size_t)b * NPTS * FEAT;
        for (int u = t; u < NPTS; u += 256) {
            float2 c; c.x = ev[u * FEAT + 0]; c.y = ev[u * FEAT + 1];
            s_xy[u] = c;
        }
        __syncthreads();

        int pl   = t >> 1;           // local point 0..127
        int half = t & 1;            // candidate half
        int i    = seg + pl;         // point index in batch
        float xi = s_xy[i].x, yi = s_xy[i].y;

        float bd[17]; int bi[17];
#pragma unroll
        for (int s = 0; s < 17; s++) { bd[s] = 3.4e38f; bi[s] = 0; }

        int j0 = half * 256;
        for (int j = j0; j < j0 + 256; j++) {
            float2 c = s_xy[j];
            float dx = xi - c.x;
            float dy = yi - c.y;
            float d2 = fmaf(dx, dx, dy * dy);
            if (d2 < bd[16]) {
                float cd = d2; int cj = j;
#pragma unroll
                for (int s = 0; s < 17; s++) {
                    bool lt  = cd < bd[s];               // ties: keep old (earlier j)
                    float mn = fminf(cd, bd[s]);
                    float mx = fmaxf(cd, bd[s]);
                    int   ni = lt ? cj : bi[s];
                    int   xj = lt ? bi[s] : cj;
                    bd[s] = mn; bi[s] = ni;
                    cd    = mx; cj    = xj;
                }
            }
        }

        // bitonic top-17 merge of the two halves (A = even lane = low j)
        float Cd[17]; int Ci[17];
#pragma unroll
        for (int s = 0; s < 17; s++) {
            float od = __shfl_xor_sync(0xffffffffu, bd[16 - s], 1);
            int   oi = __shfl_xor_sync(0xffffffffu, bi[16 - s], 1);
            bool tk = od < bd[s];        // strict: value tie keeps own (A on even)
            Cd[s] = tk ? od : bd[s];
            Ci[s] = tk ? oi : bi[s];
        }
        // lexicographic min of C = rank-0 (self or d=0 duplicate) -> drop it
        float md = Cd[0]; int mi = Ci[0]; int mpos = 0;
#pragma unroll
        for (int s = 1; s < 17; s++) {
            bool l = (Cd[s] < md) || (Cd[s] == md && Ci[s] < mi);
            md = l ? Cd[s] : md; mi = l ? Ci[s] : mi; mpos = l ? s : mpos;
        }
        if (half == 0) {
            int* o = g_nbr + ((size_t)b * NPTS + i) * KNN;
#pragma unroll
            for (int s = 0; s < 17; s++)
                if (s != mpos) o[s - (s > mpos)] = Ci[s];
        }
    } else {
        // ================= P/Q GEMM =================
        float4* wa = (float4*)sbuf;        // W1 rows 0..31  (x part), [f*32+c]
        float4* wb = wa + FEAT * 32;       // W1 rows 32..63 (nbr-x part)
        const float4* w4 = (const float4*)W1;   // 64 rows x 32 float4
        for (int u = t; u < 2048; u += 256) {
            if (u < 1024) wa[u] = w4[u]; else wb[u - 1024] = w4[u];
        }
        __syncthreads();

        int w = t >> 5, lane = t & 31;
        size_t pt = (size_t)(blockIdx.x - KNNBLK) * 8 + w;
        float ev = events[pt * FEAT + lane];

        float4 aA = {0.f, 0.f, 0.f, 0.f};
        float4 aB = {0.f, 0.f, 0.f, 0.f};
#pragma unroll
        for (int f = 0; f < FEAT; f++) {
            float ef = __shfl_sync(0xffffffffu, ev, f);
            float4 a = wa[f * 32 + lane];
            float4 b = wb[f * 32 + lane];
            aA.x = fmaf(ef, a.x, aA.x); aA.y = fmaf(ef, a.y, aA.y);
            aA.z = fmaf(ef, a.z, aA.z); aA.w = fmaf(ef, a.w, aA.w);
            aB.x = fmaf(ef, b.x, aB.x); aB.y = fmaf(ef, b.y, aB.y);
            aB.z = fmaf(ef, b.z, aB.z); aB.w = fmaf(ef, b.w, aB.w);
        }
        float4 bv = ((const float4*)b1)[lane];
        float4 p;
        p.x = aA.x - aB.x + bv.x; p.y = aA.y - aB.y + bv.y;
        p.z = aA.z - aB.z + bv.z; p.w = aA.w - aB.w + bv.w;
        ((float4*)g_P)[pt * 32 + lane] = p;
        ((float4*)g_Q)[pt * 32 + lane] = aB;
    }
}

// ---------------------------------------------------------------------------
// Kernel 2: fused gather + relu + (16x128)@(128x64) + relu + mean over k.
// WARP-AUTONOMOUS: each warp grid-strides over points; no block barriers in
// the loop (h1 slab is per-warp). Phase A: lane owns h = 4*lane..4*lane+3
// (LDG.128 + STS.128 per k). Phase B: packed fp32x2 FMA (FFMA2).
// ---------------------------------------------------------------------------
__device__ __forceinline__ unsigned long long dup_f32(float s) {
    unsigned long long r;
    asm("mov.b64 %0, {%1, %1};" : "=l"(r) : "r"(__float_as_uint(s)));
    return r;
}
__device__ __forceinline__ void fma2(unsigned long long& acc,
                                     unsigned long long a, unsigned long long b) {
    asm("fma.rn.f32x2 %0, %1, %2, %0;" : "+l"(acc) : "l"(a), "l"(b));
}
__device__ __forceinline__ void unpack2(unsigned long long v, float& lo, float& hi) {
    unsigned l, h;
    asm("mov.b64 {%0, %1}, %2;" : "=r"(l), "=r"(h) : "l"(v));
    lo = __uint_as_float(l); hi = __uint_as_float(h);
}

__global__ void __launch_bounds__(256, 2) edge_kernel(const float* __restrict__ W2,
                                                      const float* __restrict__ b2,
                                                      float* __restrict__ out) {
    extern __shared__ float smem[];
    float* w2s = smem;                    // 8192 floats (32 KB)
    float* h1  = w2s + HID * DOUT;        // 8 warps * 16 * 132

    int t = threadIdx.x;
    int w = t >> 5, lane = t & 31;
    int kg = lane >> 3, dg = lane & 7;

    for (int u = t; u < HID * DOUT / 4; u += 256)
        ((float4*)w2s)[u] = ((const float4*)W2)[u];
    __syncthreads();                       // only block-wide barrier

    float b2v[8];
#pragma unroll
    for (int dd = 0; dd < 8; dd++) b2v[dd] = b2[dg * 8 + dd];

    float* h1w = h1 + w * (KNN * H1STR);
    const float4* a0p = (const float4*)(h1w + (kg     ) * H1STR);
    const float4* a1p = (const float4*)(h1w + (kg +  4) * H1STR);
    const float4* a2p = (const float4*)(h1w + (kg +  8) * H1STR);
    const float4* a3p = (const float4*)(h1w + (kg + 12) * H1STR);
    const ulonglong2* w2u = (const ulonglong2*)w2s;   // W2 row = 16 ull2

    int gw = blockIdx.x * 8 + w;           // global warp id (EWARPS total)

    for (int pt = gw; pt < BN; pt += EWARPS) {
        int bb = pt & ~(NPTS - 1);         // batch base

        // prefetch the 16 neighbor indices (lanes 0..15)
        int jreg = 0;
        if (lane < KNN) jreg = __ldg(g_nbr + (size_t)pt * KNN + lane);
        // P row: lane owns h = 4*lane .. 4*lane+3
        float4 p4 = __ldg((const float4*)(g_P + (size_t)pt * HID) + lane);

        // ---- phase A: h1[k][h] = relu(P[h] + Q[nbr_k][h])
#pragma unroll 4
        for (int k = 0; k < KNN; k++) {
            int j = __shfl_sync(0xffffffffu, jreg, k);
            float4 q4 = __ldg((const float4*)(g_Q + (size_t)(bb + j) * HID) + lane);
            float4 v;
            v.x = fmaxf(p4.x + q4.x, 0.0f);
            v.y = fmaxf(p4.y + q4.y, 0.0f);
            v.z = fmaxf(p4.z + q4.z, 0.0f);
            v.w = fmaxf(p4.w + q4.w, 0.0f);
            *(float4*)(h1w + k * H1STR + lane * 4) = v;
        }
        __syncwarp();

        // ---- phase B: packed-pair accumulate. acc2[kk][p] = (d=2p, d=2p+1)
        unsigned long long acc2[4][4];
#pragma unroll
        for (int a = 0; a < 4; a++)
#pragma unroll
            for (int p = 0; p < 4; p++) acc2[a][p] = 0ull;

#define EK_STEP(COMP, HH)                                                     \
        {                                                                     \
            ulonglong2 wA = w2u[(HH) * 16 + dg * 2];                          \
            ulonglong2 wB = w2u[(HH) * 16 + dg * 2 + 1];                      \
            unsigned long long s0 = dup_f32(a0.COMP);                         \
            unsigned long long s1 = dup_f32(a1.COMP);                         \
            unsigned long long s2 = dup_f32(a2.COMP);                         \
            unsigned long long s3 = dup_f32(a3.COMP);                         \
            fma2(acc2[0][0], s0, wA.x); fma2(acc2[0][1], s0, wA.y);           \
            fma2(acc2[0][2], s0, wB.x); fma2(acc2[0][3], s0, wB.y);           \
            fma2(acc2[1][0], s1, wA.x); fma2(acc2[1][1], s1, wA.y);           \
            fma2(acc2[1][2], s1, wB.x); fma2(acc2[1][3], s1, wB.y);           \
            fma2(acc2[2][0], s2, wA.x); fma2(acc2[2][1], s2, wA.y);           \
            fma2(acc2[2][2], s2, wB.x); fma2(acc2[2][3], s2, wB.y);           \
            fma2(acc2[3][0], s3, wA.x); fma2(acc2[3][1], s3, wA.y);           \
            fma2(acc2[3][2], s3, wB.x); fma2(acc2[3][3], s3, wB.y);           \
        }

#pragma unroll 4
        for (int hq = 0; hq < HID / 4; hq++) {
            float4 a0 = a0p[hq], a1 = a1p[hq], a2 = a2p[hq], a3 = a3p[hq];
            EK_STEP(x, hq * 4 + 0)
            EK_STEP(y, hq * 4 + 1)
            EK_STEP(z, hq * 4 + 2)
            EK_STEP(w, hq * 4 + 3)
        }
#undef EK_STEP

        // relu(+b2) per k, sum 4 local k, shuffle-reduce across 4 k-groups
        float s[8];
#pragma unroll
        for (int p = 0; p < 4; p++) {
            float v0l, v0h, v1l, v1h, v2l, v2h, v3l, v3h;
            unpack2(acc2[0][p], v0l, v0h);
            unpack2(acc2[1][p], v1l, v1h);
            unpack2(acc2[2][p], v2l, v2h);
            unpack2(acc2[3][p], v3l, v3h);
            float bl = b2v[2 * p], bh = b2v[2 * p + 1];
            s[2 * p] = fmaxf(v0l + bl, 0.0f) + fmaxf(v1l + bl, 0.0f)
                     + fmaxf(v2l + bl, 0.0f) + fmaxf(v3l + bl, 0.0f);
            s[2 * p + 1] = fmaxf(v0h + bh, 0.0f) + fmaxf(v1h + bh, 0.0f)
                         + fmaxf(v2h + bh, 0.0f) + fmaxf(v3h + bh, 0.0f);
        }
#pragma unroll
        for (int dd = 0; dd < 8; dd++) {
            s[dd] += __shfl_xor_sync(0xffffffffu, s[dd], 8);
            s[dd] += __shfl_xor_sync(0xffffffffu, s[dd], 16);
        }
        if (kg == 0) {
            float* op = out + (size_t)pt * DOUT + dg * 8;
            float4 v0 = {s[0] * 0.0625f, s[1] * 0.0625f, s[2] * 0.0625f, s[3] * 0.0625f};
            float4 v1 = {s[4] * 0.0625f, s[5] * 0.0625f, s[6] * 0.0625f, s[7] * 0.0625f};
            ((float4*)op)[0] = v0;
            ((float4*)op)[1] = v1;
        }
        __syncwarp();   // phase-B reads done before next iter's phase-A stores
    }
}

// ---------------------------------------------------------------------------
extern "C" void kernel_launch(void* const* d_in, const int* in_sizes, int n_in,
                              void* d_out, int out_size) {
    const float* events = (const float*)d_in[0];   // (128,512,32)
    const float* W1     = (const float*)d_in[1];   // (64,128)
    const float* b1     = (const float*)d_in[2];   // (128)
    const float* W2     = (const float*)d_in[3];   // (128,64)
    const float* b2     = (const float*)d_in[4];   // (64)
    float* out = (float*)d_out;                    // (128,512,64)

    const int smem3 = (HID * DOUT + 8 * KNN * H1STR) * 4;   // ~98 KB
    cudaFuncSetAttribute(edge_kernel, cudaFuncAttributeMaxDynamicSharedMemorySize, smem3);

    knn_pq_kernel<<<KNNBLK + PQBLK, 256>>>(events, W1, b1);
    edge_kernel<<<EGRID, 256, smem3>>>(W2, b2, out);
}

// round 9
// speedup vs baseline: 1.7653x; 1.2531x over previous
#include <cuda_runtime.h>
#include <cstdint>

#define BN      65536
#define NPTS    512
#define KNN     16
#define HID     128
#define DOUT    64
#define FEAT    32
#define KNNBLK  512
#define PQBLK   8192
#define NTILES  4096        // 16 points per tile
#define EGRID   148
#define H1SLAB  (KNN * 132) // words per point slab

// Scratch (allocation-free rule: __device__ globals)
__device__ float g_P[BN * HID];
__device__ float g_Q[BN * HID];
__device__ int   g_nbr[BN * KNN];

__device__ __forceinline__ uint32_t f2tf32(float f) {
    uint32_t r;
    asm("cvt.rna.tf32.f32 %0, %1;" : "=r"(r) : "f"(f));
    return r;
}
// D(16x8) += A(16x8 tf32, row) * B(8x8 tf32, col)
__device__ __forceinline__ void mma_tf32(float4& c, uint32_t a0, uint32_t a1,
                                         uint32_t a2, uint32_t a3,
                                         uint32_t b0, uint32_t b1) {
    asm volatile(
        "mma.sync.aligned.m16n8k8.row.col.f32.tf32.tf32.f32 "
        "{%0,%1,%2,%3}, {%4,%5,%6,%7}, {%8,%9}, {%0,%1,%2,%3};"
        : "+f"(c.x), "+f"(c.y), "+f"(c.z), "+f"(c.w)
        : "r"(a0), "r"(a1), "r"(a2), "r"(a3), "r"(b0), "r"(b1));
}

// ---------------------------------------------------------------------------
// Fused kernel 1: blocks [0,512) KNN (2 threads/point); rest P/Q GEMM.
// (unchanged from R5 — passing)
// ---------------------------------------------------------------------------
__global__ void __launch_bounds__(256) knn_pq_kernel(const float* __restrict__ events,
                                                     const float* __restrict__ W1,
                                                     const float* __restrict__ b1) {
    __shared__ float sbuf[8192];   // 32 KB
    int t = threadIdx.x;

    if (blockIdx.x < KNNBLK) {
        float2* s_xy = (float2*)sbuf;
        int b   = blockIdx.x >> 2;
        int seg = (blockIdx.x & 3) * 128;
        const float* ev = events + (size_t)b * NPTS * FEAT;
        for (int u = t; u < NPTS; u += 256) {
            float2 c; c.x = ev[u * FEAT + 0]; c.y = ev[u * FEAT + 1];
            s_xy[u] = c;
        }
        __syncthreads();

        int pl   = t >> 1;
        int half = t & 1;
        int i    = seg + pl;
        float xi = s_xy[i].x, yi = s_xy[i].y;

        float bd[17]; int bi[17];
#pragma unroll
        for (int s = 0; s < 17; s++) { bd[s] = 3.4e38f; bi[s] = 0; }

        int j0 = half * 256;
        for (int j = j0; j < j0 + 256; j++) {
            float2 c = s_xy[j];
            float dx = xi - c.x;
            float dy = yi - c.y;
            float d2 = fmaf(dx, dx, dy * dy);
            if (d2 < bd[16]) {
                float cd = d2; int cj = j;
#pragma unroll
                for (int s = 0; s < 17; s++) {
                    bool lt  = cd < bd[s];
                    float mn = fminf(cd, bd[s]);
                    float mx = fmaxf(cd, bd[s]);
                    int   ni = lt ? cj : bi[s];
                    int   xj = lt ? bi[s] : cj;
                    bd[s] = mn; bi[s] = ni;
                    cd    = mx; cj    = xj;
                }
            }
        }

        float Cd[17]; int Ci[17];
#pragma unroll
        for (int s = 0; s < 17; s++) {
            float od = __shfl_xor_sync(0xffffffffu, bd[16 - s], 1);
            int   oi = __shfl_xor_sync(0xffffffffu, bi[16 - s], 1);
            bool tk = od < bd[s];
            Cd[s] = tk ? od : bd[s];
            Ci[s] = tk ? oi : bi[s];
        }
        float md = Cd[0]; int mi = Ci[0]; int mpos = 0;
#pragma unroll
        for (int s = 1; s < 17; s++) {
            bool l = (Cd[s] < md) || (Cd[s] == md && Ci[s] < mi);
            md = l ? Cd[s] : md; mi = l ? Ci[s] : mi; mpos = l ? s : mpos;
        }
        if (half == 0) {
            int* o = g_nbr + ((size_t)b * NPTS + i) * KNN;
#pragma unroll
            for (int s = 0; s < 17; s++)
                if (s != mpos) o[s - (s > mpos)] = Ci[s];
        }
    } else {
        float4* wa = (float4*)sbuf;
        float4* wb = wa + FEAT * 32;
        const float4* w4 = (const float4*)W1;
        for (int u = t; u < 2048; u += 256) {
            if (u < 1024) wa[u] = w4[u]; else wb[u - 1024] = w4[u];
        }
        __syncthreads();

        int w = t >> 5, lane = t & 31;
        size_t pt = (size_t)(blockIdx.x - KNNBLK) * 8 + w;
        float ev = events[pt * FEAT + lane];

        float4 aA = {0.f, 0.f, 0.f, 0.f};
        float4 aB = {0.f, 0.f, 0.f, 0.f};
#pragma unroll
        for (int f = 0; f < FEAT; f++) {
            float ef = __shfl_sync(0xffffffffu, ev, f);
            float4 a = wa[f * 32 + lane];
            float4 b = wb[f * 32 + lane];
            aA.x = fmaf(ef, a.x, aA.x); aA.y = fmaf(ef, a.y, aA.y);
            aA.z = fmaf(ef, a.z, aA.z); aA.w = fmaf(ef, a.w, aA.w);
            aB.x = fmaf(ef, b.x, aB.x); aB.y = fmaf(ef, b.y, aB.y);
            aB.z = fmaf(ef, b.z, aB.z); aB.w = fmaf(ef, b.w, aB.w);
        }
        float4 bv = ((const float4*)b1)[lane];
        float4 p;
        p.x = aA.x - aB.x + bv.x; p.y = aA.y - aB.y + bv.y;
        p.z = aA.z - aB.z + bv.z; p.w = aA.w - aB.w + bv.w;
        ((float4*)g_P)[pt * 32 + lane] = p;
        ((float4*)g_Q)[pt * 32 + lane] = aB;
    }
}

// ---------------------------------------------------------------------------
// Kernel 2: gather + relu -> tf32 h1 slab (per point), then layer 2 via
// mma.sync m16n8k8 tf32. Warp = 2 points (B fragments reused); block = 16
// points; no block barriers in the loop.
//
// Fragment mapping (PTX m16n8k8, lane = 4*g... lane>>2 = g, lane&3 = tig):
//   A: a0=(g, tig) a1=(g+8, tig) a2=(g, tig+4) a3=(g+8, tig+4)  [row, col]
//   B: b0=(tig, g) b1=(tig+4, g)                                [k  , n  ]
//   D: c0=(g, 2tig) c1=(g, 2tig+1) c2=(g+8, 2tig) c3=(g+8, 2tig+1)
// Btab smem layout: word[(kb*8+nb)*64 + lane*2 + r] = tf32(W2[kb*8+tig+r*4][nb*8+g])
// ---------------------------------------------------------------------------
__global__ void __launch_bounds__(256) edge_kernel(const float* __restrict__ W2,
                                                   const float* __restrict__ b2,
                                                   float* __restrict__ out) {
    extern __shared__ __align__(16) char smem[];
    uint32_t* Btab = (uint32_t*)smem;                 // 32 KB
    uint32_t* h1   = (uint32_t*)(smem + 32768);       // 16 slabs * 2112 words

    int t = threadIdx.x, w = t >> 5, lane = t & 31;
    int tig = lane & 3, g = lane >> 2;

    // ---- one-time: bake W2 into fragment-ordered tf32 table
    for (int idx = t; idx < 16 * 8 * 64; idx += 256) {
        int r  = idx & 1;
        int ln = (idx >> 1) & 31;
        int fi = idx >> 6;
        int nb = fi & 7, kb = fi >> 3;
        int bt = ln & 3, bg = ln >> 2;
        Btab[idx] = f2tf32(W2[(kb * 8 + bt + r * 4) * DOUT + nb * 8 + bg]);
    }
    __syncthreads();

    float b2c0[8], b2c1[8];
#pragma unroll
    for (int nb = 0; nb < 8; nb++) {
        b2c0[nb] = __ldg(b2 + nb * 8 + 2 * tig);
        b2c1[nb] = __ldg(b2 + nb * 8 + 2 * tig + 1);
    }

    uint32_t* slab[2] = { h1 + (2 * w) * H1SLAB, h1 + (2 * w + 1) * H1SLAB };

    for (int gi = blockIdx.x; gi < NTILES; gi += EGRID) {
        int base = gi * 16;
        int bb   = base & ~(NPTS - 1);

        // ---- phase A: h1[p][k][h] = tf32(relu(P[h] + Q[nbr_k][h]))
#pragma unroll
        for (int p = 0; p < 2; p++) {
            int pt = base + 2 * w + p;
            int jreg = 0;
            if (lane < KNN) jreg = __ldg(g_nbr + (size_t)pt * KNN + lane);
            float4 p4 = __ldg((const float4*)(g_P + (size_t)pt * HID) + lane);
            uint32_t* sl = slab[p];
#pragma unroll 4
            for (int k = 0; k < KNN; k++) {
                int j = __shfl_sync(0xffffffffu, jreg, k);
                float4 q4 = __ldg((const float4*)(g_Q + (size_t)(bb + j) * HID) + lane);
                uint4 v;
                v.x = f2tf32(fmaxf(p4.x + q4.x, 0.0f));
                v.y = f2tf32(fmaxf(p4.y + q4.y, 0.0f));
                v.z = f2tf32(fmaxf(p4.z + q4.z, 0.0f));
                v.w = f2tf32(fmaxf(p4.w + q4.w, 0.0f));
                *(uint4*)(sl + k * 132 + lane * 4) = v;
            }
        }
        __syncwarp();

        // ---- phase B: 2 points x 16 kb x 8 nb MMAs, B fragments shared
        float4 acc[2][8];
#pragma unroll
        for (int p = 0; p < 2; p++)
#pragma unroll
            for (int nb = 0; nb < 8; nb++)
                acc[p][nb] = make_float4(0.f, 0.f, 0.f, 0.f);

#pragma unroll 4
        for (int kb = 0; kb < 16; kb++) {
            uint32_t a0[2], a1[2], a2[2], a3[2];
#pragma unroll
            for (int p = 0; p < 2; p++) {
                const uint32_t* sl = slab[p] + kb * 8 + tig;
                a0[p] = sl[g * 132];
                a2[p] = sl[g * 132 + 4];
                a1[p] = sl[(g + 8) * 132];
                a3[p] = sl[(g + 8) * 132 + 4];
            }
            const uint32_t* bt_kb = Btab + kb * 8 * 64;
#pragma unroll
            for (int nb = 0; nb < 8; nb++) {
                unsigned long long bp =
                    *(const unsigned long long*)(bt_kb + nb * 64 + lane * 2);
                uint32_t b0 = (uint32_t)bp;
                uint32_t b1 = (uint32_t)(bp >> 32);
                mma_tf32(acc[0][nb], a0[0], a1[0], a2[0], a3[0], b0, b1);
                mma_tf32(acc[1][nb], a0[1], a1[1], a2[1], a3[1], b0, b1);
            }
        }

        // ---- epilogue: relu(+b2), sum 16 k-rows, mean, store
#pragma unroll
        for (int p = 0; p < 2; p++) {
            int pt = base + 2 * w + p;
#pragma unroll
            for (int nb = 0; nb < 8; nb++) {
                float v0 = fmaxf(acc[p][nb].x + b2c0[nb], 0.0f);
                float v1 = fmaxf(acc[p][nb].y + b2c1[nb], 0.0f);
                float v2 = fmaxf(acc[p][nb].z + b2c0[nb], 0.0f);
                float v3 = fmaxf(acc[p][nb].w + b2c1[nb], 0.0f);
                float s0 = v0 + v2;
                float s1 = v1 + v3;
                s0 += __shfl_xor_sync(0xffffffffu, s0, 4);
                s1 += __shfl_xor_sync(0xffffffffu, s1, 4);
                s0 += __shfl_xor_sync(0xffffffffu, s0, 8);
                s1 += __shfl_xor_sync(0xffffffffu, s1, 8);
                s0 += __shfl_xor_sync(0xffffffffu, s0, 16);
                s1 += __shfl_xor_sync(0xffffffffu, s1, 16);
                if (g == 0) {
                    float2 o = { s0 * 0.0625f, s1 * 0.0625f };
                    *(float2*)(out + (size_t)pt * DOUT + nb * 8 + 2 * tig) = o;
                }
            }
        }
        __syncwarp();   // epilogue A-reads done before next phase-A stores
    }
}

// ---------------------------------------------------------------------------
extern "C" void kernel_launch(void* const* d_in, const int* in_sizes, int n_in,
                              void* d_out, int out_size) {
    const float* events = (const float*)d_in[0];   // (128,512,32)
    const float* W1     = (const float*)d_in[1];   // (64,128)
    const float* b1     = (const float*)d_in[2];   // (128)
    const float* W2     = (const float*)d_in[3];   // (128,64)
    const float* b2     = (const float*)d_in[4];   // (64)
    float* out = (float*)d_out;                    // (128,512,64)

    const int smem2 = 32768 + 16 * H1SLAB * 4;     // 32KB + 135KB = ~168KB
    cudaFuncSetAttribute(edge_kernel, cudaFuncAttributeMaxDynamicSharedMemorySize, smem2);

    knn_pq_kernel<<<KNNBLK + PQBLK, 256>>>(events, W1, b1);
    edge_kernel<<<EGRID, 256, smem2>>>(W2, b2, out);
}

// round 12
// speedup vs baseline: 3.2617x; 1.8477x over previous
#include <cuda_runtime.h>
#include <cstdint>

#define BN      65536
#define NPTS    512
#define KNN     16
#define HID     128
#define DOUT    64
#define FEAT    32
#define KNNBLK  512
#define PQBLK   8192
#define NTILES  4096        // 16 points per tile
#define EGRID   296
#define SLABW   (16 * 68 + 4)   // words per point slab (h-chunk of 64, padded)

// Scratch (allocation-free rule: __device__ globals)
__device__ float g_P[BN * HID];
__device__ float g_Q[BN * HID];
__device__ int   g_nbr[BN * KNN];

__device__ __forceinline__ uint32_t f2tf32(float f) {
    uint32_t r;
    asm("cvt.rna.tf32.f32 %0, %1;" : "=r"(r) : "f"(f));
    return r;
}
__device__ __forceinline__ void mma_tf32(float4& c, uint32_t a0, uint32_t a1,
                                         uint32_t a2, uint32_t a3,
                                         uint32_t b0, uint32_t b1) {
    asm volatile(
        "mma.sync.aligned.m16n8k8.row.col.f32.tf32.tf32.f32 "
        "{%0,%1,%2,%3}, {%4,%5,%6,%7}, {%8,%9}, {%0,%1,%2,%3};"
        : "+f"(c.x), "+f"(c.y), "+f"(c.z), "+f"(c.w)
        : "r"(a0), "r"(a1), "r"(a2), "r"(a3), "r"(b0), "r"(b1));
}

// ---------------------------------------------------------------------------
// Fused kernel 1: blocks [0,512) KNN; rest P/Q GEMM (W1 via __ldg, no smem).
// Only 4 KB static smem -> knn co-residency is register-limited (4 blocks/SM).
// ---------------------------------------------------------------------------
__global__ void __launch_bounds__(256) knn_pq_kernel(const float* __restrict__ events,
                                                     const float* __restrict__ W1,
                                                     const float* __restrict__ b1) {
    __shared__ float2 s_xy[NPTS];   // 4 KB (knn only)
    int t = threadIdx.x;

    if (blockIdx.x < KNNBLK) {
        int b   = blockIdx.x >> 2;
        int seg = (blockIdx.x & 3) * 128;
        const float* ev = events + (size_t)b * NPTS * FEAT;
        for (int u = t; u < NPTS; u += 256) {
            float2 c; c.x = ev[u * FEAT + 0]; c.y = ev[u * FEAT + 1];
            s_xy[u] = c;
        }
        __syncthreads();

        int pl   = t >> 1;
        int half = t & 1;
        int i    = seg + pl;
        float xi = s_xy[i].x, yi = s_xy[i].y;

        float bd[17]; int bi[17];
#pragma unroll
        for (int s = 0; s < 17; s++) { bd[s] = 3.4e38f; bi[s] = 0; }

        int j0 = half * 256;
        for (int j = j0; j < j0 + 256; j++) {
            float2 c = s_xy[j];
            float dx = xi - c.x;
            float dy = yi - c.y;
            float d2 = fmaf(dx, dx, dy * dy);
            if (d2 < bd[16]) {
                float cd = d2; int cj = j;
#pragma unroll
                for (int s = 0; s < 17; s++) {
                    bool lt  = cd < bd[s];
                    float mn = fminf(cd, bd[s]);
                    float mx = fmaxf(cd, bd[s]);
                    int   ni = lt ? cj : bi[s];
                    int   xj = lt ? bi[s] : cj;
                    bd[s] = mn; bi[s] = ni;
                    cd    = mx; cj    = xj;
                }
            }
        }

        float Cd[17]; int Ci[17];
#pragma unroll
        for (int s = 0; s < 17; s++) {
            float od = __shfl_xor_sync(0xffffffffu, bd[16 - s], 1);
            int   oi = __shfl_xor_sync(0xffffffffu, bi[16 - s], 1);
            bool tk = od < bd[s];
            Cd[s] = tk ? od : bd[s];
            Ci[s] = tk ? oi : bi[s];
        }
        float md = Cd[0]; int mi = Ci[0]; int mpos = 0;
#pragma unroll
        for (int s = 1; s < 17; s++) {
            bool l = (Cd[s] < md) || (Cd[s] == md && Ci[s] < mi);
            md = l ? Cd[s] : md; mi = l ? Ci[s] : mi; mpos = l ? s : mpos;
        }
        if (half == 0) {
            int* o = g_nbr + ((size_t)b * NPTS + i) * KNN;
#pragma unroll
            for (int s = 0; s < 17; s++)
                if (s != mpos) o[s - (s > mpos)] = Ci[s];
        }
    } else {
        // ---- P/Q GEMM: W1 straight from L1 (uniform across warps)
        int w = t >> 5, lane = t & 31;
        size_t pt = (size_t)(blockIdx.x - KNNBLK) * 8 + w;
        float ev = events[pt * FEAT + lane];
        const float4* w4 = (const float4*)W1;

        float4 aA = {0.f, 0.f, 0.f, 0.f};
        float4 aB = {0.f, 0.f, 0.f, 0.f};
#pragma unroll
        for (int f = 0; f < FEAT; f++) {
            float ef = __shfl_sync(0xffffffffu, ev, f);
            float4 a = __ldg(w4 + f * 32 + lane);
            float4 b = __ldg(w4 + (f + FEAT) * 32 + lane);
            aA.x = fmaf(ef, a.x, aA.x); aA.y = fmaf(ef, a.y, aA.y);
            aA.z = fmaf(ef, a.z, aA.z); aA.w = fmaf(ef, a.w, aA.w);
            aB.x = fmaf(ef, b.x, aB.x); aB.y = fmaf(ef, b.y, aB.y);
            aB.z = fmaf(ef, b.z, aB.z); aB.w = fmaf(ef, b.w, aB.w);
        }
        float4 bv = __ldg((const float4*)b1 + lane);
        float4 p;
        p.x = aA.x - aB.x + bv.x; p.y = aA.y - aB.y + bv.y;
        p.z = aA.z - aB.z + bv.z; p.w = aA.w - aB.w + bv.w;
        ((float4*)g_P)[pt * 32 + lane] = p;
        ((float4*)g_Q)[pt * 32 + lane] = aB;
    }
}

// ---------------------------------------------------------------------------
// Kernel 2: K-split edge kernel. Per chunk c (h in [c*64, c*64+64)):
// phase A gathers relu(P+Q) for BOTH points (half-warp each) into per-warp
// slabs, phase B runs 8 kb x 8 nb tf32 MMAs accumulating across chunks.
// smem ~100 KB -> 2 blocks/SM.
// ---------------------------------------------------------------------------
__global__ void __launch_bounds__(256, 2) edge_kernel(const float* __restrict__ W2,
                                                      const float* __restrict__ b2,
                                                      float* __restrict__ out) {
    extern __shared__ __align__(16) char smem[];
    uint32_t* Btab = (uint32_t*)smem;                 // 32 KB
    uint32_t* h1   = (uint32_t*)(smem + 32768);       // 8 warps * 2 * SLABW

    int t = threadIdx.x, w = t >> 5, lane = t & 31;
    int tig = lane & 3, g = lane >> 2;
    int half = lane >> 4, hl = lane & 15;

    // bake W2 into fragment-ordered tf32 table
    for (int idx = t; idx < 16 * 8 * 64; idx += 256) {
        int r  = idx & 1;
        int ln = (idx >> 1) & 31;
        int fi = idx >> 6;
        int nb = fi & 7, kb = fi >> 3;
        int bt = ln & 3, bg = ln >> 2;
        Btab[idx] = f2tf32(W2[(kb * 8 + bt + r * 4) * DOUT + nb * 8 + bg]);
    }
    __syncthreads();

    float b2c0[8], b2c1[8];
#pragma unroll
    for (int nb = 0; nb < 8; nb++) {
        b2c0[nb] = __ldg(b2 + nb * 8 + 2 * tig);
        b2c1[nb] = __ldg(b2 + nb * 8 + 2 * tig + 1);
    }

    uint32_t* slab0 = h1 + (2 * w) * SLABW;
    uint32_t* slab1 = slab0 + SLABW;
    uint32_t* mysl  = half ? slab1 : slab0;

    for (int gi = blockIdx.x; gi < NTILES; gi += EGRID) {
        int base = gi * 16;
        int bb   = base & ~(NPTS - 1);
        int pt   = base + 2 * w + half;     // this half-warp's point

        // coalesced: lanes 0..31 cover nbr lists of both points
        int jreg = __ldg(g_nbr + (size_t)(base + 2 * w) * KNN + lane);

        float4 acc[2][8];
#pragma unroll
        for (int p = 0; p < 2; p++)
#pragma unroll
            for (int nb = 0; nb < 8; nb++)
                acc[p][nb] = make_float4(0.f, 0.f, 0.f, 0.f);

#pragma unroll
        for (int c = 0; c < 2; c++) {
            // ---- phase A (chunk c): h1[k][h] = tf32(relu(P[h]+Q[nbr_k][h]))
            float4 p4 = __ldg((const float4*)(g_P + (size_t)pt * HID + c * 64) + hl);
#pragma unroll 4
            for (int k = 0; k < KNN; k++) {
                int j = __shfl_sync(0xffffffffu, jreg, k + 16 * half);
                float4 q4 = __ldg((const float4*)(g_Q + (size_t)(bb + j) * HID + c * 64) + hl);
                uint4 v;
                v.x = f2tf32(fmaxf(p4.x + q4.x, 0.0f));
                v.y = f2tf32(fmaxf(p4.y + q4.y, 0.0f));
                v.z = f2tf32(fmaxf(p4.z + q4.z, 0.0f));
                v.w = f2tf32(fmaxf(p4.w + q4.w, 0.0f));
                *(uint4*)(mysl + k * 68 + hl * 4) = v;
            }
            __syncwarp();

            // ---- phase B (chunk c): 8 kb x 8 nb, 2 points
#pragma unroll 4
            for (int kb8 = 0; kb8 < 8; kb8++) {
                uint32_t a0[2], a1[2], a2[2], a3[2];
#pragma unroll
                for (int p = 0; p < 2; p++) {
                    const uint32_t* sl = (p ? slab1 : slab0) + kb8 * 8 + tig;
                    a0[p] = sl[g * 68];
                    a2[p] = sl[g * 68 + 4];
                    a1[p] = sl[(g + 8) * 68];
                    a3[p] = sl[(g + 8) * 68 + 4];
                }
                const uint32_t* bt_kb = Btab + (c * 8 + kb8) * 512;
#pragma unroll
                for (int nb = 0; nb < 8; nb++) {
                    unsigned long long bp =
                        *(const unsigned long long*)(bt_kb + nb * 64 + lane * 2);
                    uint32_t b0 = (uint32_t)bp;
                    uint32_t b1 = (uint32_t)(bp >> 32);
                    mma_tf32(acc[0][nb], a0[0], a1[0], a2[0], a3[0], b0, b1);
                    mma_tf32(acc[1][nb], a0[1], a1[1], a2[1], a3[1], b0, b1);
                }
            }
            __syncwarp();   // B-reads done before next chunk's A-stores
        }

        // ---- epilogue: relu(+b2), sum 16 k-rows, mean, store
#pragma unroll
        for (int p = 0; p < 2; p++) {
            int ptl = base + 2 * w + p;
#pragma unroll
            for (int nb = 0; nb < 8; nb++) {
                float v0 = fmaxf(acc[p][nb].x + b2c0[nb], 0.0f);
                float v1 = fmaxf(acc[p][nb].y + b2c1[nb], 0.0f);
                float v2 = fmaxf(acc[p][nb].z + b2c0[nb], 0.0f);
                float v3 = fmaxf(acc[p][nb].w + b2c1[nb], 0.0f);
                float s0 = v0 + v2;
                float s1 = v1 + v3;
                s0 += __shfl_xor_sync(0xffffffffu, s0, 4);
                s1 += __shfl_xor_sync(0xffffffffu, s1, 4);
                s0 += __shfl_xor_sync(0xffffffffu, s0, 8);
                s1 += __shfl_xor_sync(0xffffffffu, s1, 8);
                s0 += __shfl_xor_sync(0xffffffffu, s0, 16);
                s1 += __shfl_xor_sync(0xffffffffu, s1, 16);
                if (g == 0) {
                    float2 o = { s0 * 0.0625f, s1 * 0.0625f };
                    *(float2*)(out + (size_t)ptl * DOUT + nb * 8 + 2 * tig) = o;
                }
            }
        }
    }
}

// ---------------------------------------------------------------------------
extern "C" void kernel_launch(void* const* d_in, const int* in_sizes, int n_in,
                              void* d_out, int out_size) {
    const float* events = (const float*)d_in[0];   // (128,512,32)
    const float* W1     = (const float*)d_in[1];   // (64,128)
    const float* b1     = (const float*)d_in[2];   // (128)
    const float* W2     = (const float*)d_in[3];   // (128,64)
    const float* b2     = (const float*)d_in[4];   // (64)
    float* out = (float*)d_out;                    // (128,512,64)

    const int smem2 = 32768 + 16 * SLABW * 4;      // 32 KB + 68.25 KB
    cudaFuncSetAttribute(edge_kernel, cudaFuncAttributeMaxDynamicSharedMemorySize, smem2);

    knn_pq_kernel<<<KNNBLK + PQBLK, 256>>>(events, W1, b1);
    edge_kernel<<<EGRID, 256, smem2>>>(W2, b2, out);
}